// round 1
// baseline (speedup 1.0000x reference)
#include <cuda_runtime.h>
#include <math.h>

#define NG   256
#define HGT  512
#define WID  512
#define HW   (HGT * WID)
#define TB   128
#define PPT  4
#define NBLK (HW / (TB * PPT))   // 512

// ---- constants -------------------------------------------------------------
constexpr double TWOPI_D  = 6.283185307179586476925286766559;
constexpr float  TWOPI_F  = (float)TWOPI_D;              // matches np.float32(2*pi)
constexpr float  RC1      = (float)TWOPI_D;
constexpr float  RC2      = (float)(TWOPI_D - (double)RC1);
constexpr float  RC3      = (float)(TWOPI_D - (double)RC1 - (double)RC2);
constexpr float  INV2PI_F = (float)(1.0 / TWOPI_D);
constexpr double INV2PI_D = 1.0 / TWOPI_D;

// ---- device-global scratch (no dynamic allocation allowed) ------------------
// Compacted per-gabor parameters, SoA as float4 for LDS.128 loads:
//   p0 = (uc, vc, cos_th, sin_th)
//   p1 = (-1/(2 sig^2), -1/(2 gam^2), freq, A0)
//   p2 = (A1, A2, nB0, nB1)
//   p3 = nB2
// where A_c = amp_c * cos(phase_c), nB_c = -amp_c * sin(phase_c).
__device__ float4 g_p0[NG];
__device__ float4 g_p1[NG];
__device__ float4 g_p2[NG];
__device__ float  g_p3[NG];
__device__ int    g_cnt;

__device__ __forceinline__ float clampf(float x, float lo, float hi) {
    return fminf(fmaxf(x, lo), hi);
}

// ---- prep kernel: clamp params, build coefficients, compact dead gabors -----
__global__ void prep_kernel(const float* __restrict__ u,
                            const float* __restrict__ v,
                            const float* __restrict__ theta,
                            const float* __restrict__ rsig,
                            const float* __restrict__ rfreq,
                            const float* __restrict__ gam,
                            const float* __restrict__ psi,
                            const float* __restrict__ amp) {
    int n = threadIdx.x;   // 256 threads, 1 block

    float uc = clampf(u[n], -1.f, 1.f);
    float vc = clampf(v[n], -1.f, 1.f);
    float th = clampf(theta[n], -2.f, 2.f) * TWOPI_F;
    float sr, cr;
    sincosf(th, &sr, &cr);

    float sg  = clampf(rsig[n], 1e-5f, 5.f);
    float gm  = clampf(gam[n],  1e-5f, 5.f);
    float i2s = -1.f / (2.f * sg * sg);
    float i2g = -1.f / (2.f * gm * gm);
    float fr  = TWOPI_F / expf(rfreq[n]);

    float A[3], nB[3];
    bool keep = false;
    #pragma unroll
    for (int c = 0; c < 3; ++c) {
        float a  = clampf(amp[3 * n + c], 0.f, 1.f);
        float ph = clampf(psi[3 * n + c], -1.f, 1.f) * TWOPI_F;
        float sp, cp;
        sincosf(ph, &sp, &cp);
        A[c]  =  a * cp;
        nB[c] = -a * sp;
        keep  = keep || (a > 0.f);
    }

    // deterministic compaction (ballot + per-warp prefix sum)
    unsigned m = __ballot_sync(0xffffffffu, keep);
    __shared__ int wcnt[8];
    int wid = n >> 5, lid = n & 31;
    if (lid == 0) wcnt[wid] = __popc(m);
    __syncthreads();
    int basew = 0;
    for (int w = 0; w < wid; ++w) basew += wcnt[w];
    if (keep) {
        int pos = basew + __popc(m & ((1u << lid) - 1u));
        g_p0[pos] = make_float4(uc, vc, cr, sr);
        g_p1[pos] = make_float4(i2s, i2g, fr, A[0]);
        g_p2[pos] = make_float4(A[1], A[2], nB[0], nB[1]);
        g_p3[pos] = nB[2];
    }
    if (n == 0) {
        __syncthreads();  // no-op for lane, but keep ordering explicit
    }
    __syncthreads();
    if (n == 0) {
        int tot = 0;
        #pragma unroll
        for (int w = 0; w < 8; ++w) tot += wcnt[w];
        g_cnt = tot;
    }
}

// ---- main kernel -------------------------------------------------------------
__global__ void __launch_bounds__(TB)
gabor_kernel(const float* __restrict__ gx,
             const float* __restrict__ gy,
             float* __restrict__ out) {
    __shared__ float4 s_p0[NG];
    __shared__ float4 s_p1[NG];
    __shared__ float4 s_p2[NG];
    __shared__ float  s_p3[NG];

    int cnt = g_cnt;
    for (int i = threadIdx.x; i < cnt; i += TB) {
        s_p0[i] = g_p0[i];
        s_p1[i] = g_p1[i];
        s_p2[i] = g_p2[i];
        s_p3[i] = g_p3[i];
    }
    __syncthreads();

    const int base = blockIdx.x * (TB * PPT);

    float px[PPT], py[PPT];
    float acc0[PPT], acc1[PPT], acc2[PPT];
    #pragma unroll
    for (int p = 0; p < PPT; ++p) {
        int idx = base + p * TB + threadIdx.x;
        px[p] = gx[idx];
        py[p] = gy[idx];
        acc0[p] = 0.f; acc1[p] = 0.f; acc2[p] = 0.f;
    }

    for (int n = 0; n < cnt; ++n) {
        float4 p0 = s_p0[n];
        float4 p1 = s_p1[n];

        float xr[PPT], arg[PPT];
        bool act = false;
        #pragma unroll
        for (int p = 0; p < PPT; ++p) {
            float dx  = px[p] - p0.x;
            float dy  = py[p] - p0.y;
            float xrp = fmaf(dx, p0.z, dy * p0.w);        //  dx*cr + dy*sr
            float yrp = fmaf(dy, p0.z, -(dx * p0.w));     //  dy*cr - dx*sr
            xr[p]  = xrp;
            float a = fmaf(yrp * yrp, p1.y, (xrp * xrp) * p1.x);
            arg[p] = a;
            act = act || (a > -17.0f);
        }
        // warp-level skip: exp(-17)*|coef|*256 gabors <= ~2e-5 absolute — safe
        if (!__any_sync(0xffffffffu, act)) continue;

        float4 p2  = s_p2[n];
        float  nB2 = s_p3[n];

        #pragma unroll
        for (int p = 0; p < PPT; ++p) {
            float g  = __expf(fmaxf(arg[p], -80.0f));
            float fx = p1.z * xr[p];

            // range reduction to [-pi, pi]
            float r;
            if (fabsf(fx) < 1.0e7f) {
                // 3-term FMA Cody-Waite; k < 2^24 so k is exact
                float k = rintf(fx * INV2PI_F);
                r = fmaf(k, -RC1, fx);
                r = fmaf(k, -RC2, r);
                r = fmaf(k, -RC3, r);
            } else {
                // rare extreme-frequency gabor: fp64 reduction
                double xd = (double)fx;
                double q  = rint(xd * INV2PI_D);
                r = (float)fma(q, -TWOPI_D, xd);
            }

            float s, c;
            __sincosf(r, &s, &c);   // |r| <= pi: MUFU accurate (~5e-7 abs)

            float gc = g * c;
            float gs = g * s;
            acc0[p] = fmaf(gc, p1.w, fmaf(gs, p2.z, acc0[p]));
            acc1[p] = fmaf(gc, p2.x, fmaf(gs, p2.w, acc1[p]));
            acc2[p] = fmaf(gc, p2.y, fmaf(gs, nB2,  acc2[p]));
        }
    }

    #pragma unroll
    for (int p = 0; p < PPT; ++p) {
        int idx = base + p * TB + threadIdx.x;
        out[idx]          = clampf(acc0[p], -1.f, 1.f);
        out[HW + idx]     = clampf(acc1[p], -1.f, 1.f);
        out[2 * HW + idx] = clampf(acc2[p], -1.f, 1.f);
    }
}

// ---- launch ------------------------------------------------------------------
extern "C" void kernel_launch(void* const* d_in, const int* in_sizes, int n_in,
                              void* d_out, int out_size) {
    const float* gx    = (const float*)d_in[0];
    const float* gy    = (const float*)d_in[1];
    const float* u     = (const float*)d_in[2];
    const float* v     = (const float*)d_in[3];
    const float* theta = (const float*)d_in[4];
    const float* rsig  = (const float*)d_in[5];
    const float* rfreq = (const float*)d_in[6];
    const float* gam   = (const float*)d_in[7];
    const float* psi   = (const float*)d_in[8];
    const float* amp   = (const float*)d_in[9];
    float* out = (float*)d_out;

    prep_kernel<<<1, NG>>>(u, v, theta, rsig, rfreq, gam, psi, amp);
    gabor_kernel<<<NBLK, TB>>>(gx, gy, out);
}

// round 2
// speedup vs baseline: 1.0304x; 1.0304x over previous
#include <cuda_runtime.h>
#include <math.h>

#define NG   256
#define HGT  512
#define WID  512
#define HW   (HGT * WID)
#define TB   256
#define NBLK (HW / TB)   // 1024

// ---- constants -------------------------------------------------------------
constexpr double TWOPI_D  = 6.283185307179586476925286766559;
constexpr float  TWOPI_F  = (float)TWOPI_D;
constexpr float  RC1      = (float)TWOPI_D;
constexpr float  RC2      = (float)(TWOPI_D - (double)RC1);
constexpr float  INV2PI_F = (float)(1.0 / TWOPI_D);
constexpr double INV2PI_D = 1.0 / TWOPI_D;

// ---- device-global scratch ---------------------------------------------------
// Compacted per-gabor parameters, SoA as float4 for LDS.128 loads:
//   p0 = (uc, vc, cos_th, sin_th)
//   p1 = (-1/(2 sig^2), -1/(2 gam^2), freq, A0)
//   p2 = (A1, A2, nB0, nB1)
//   p3 = nB2
// where A_c = amp_c * cos(phase_c), nB_c = -amp_c * sin(phase_c).
__device__ float4 g_p0[NG];
__device__ float4 g_p1[NG];
__device__ float4 g_p2[NG];
__device__ float  g_p3[NG];
__device__ int    g_cnt;

__device__ __forceinline__ float clampf(float x, float lo, float hi) {
    return fminf(fmaxf(x, lo), hi);
}

// ---- prep kernel: clamp params, build coefficients, compact dead gabors -----
__global__ void prep_kernel(const float* __restrict__ u,
                            const float* __restrict__ v,
                            const float* __restrict__ theta,
                            const float* __restrict__ rsig,
                            const float* __restrict__ rfreq,
                            const float* __restrict__ gam,
                            const float* __restrict__ psi,
                            const float* __restrict__ amp) {
    int n = threadIdx.x;   // 256 threads, 1 block

    float uc = clampf(u[n], -1.f, 1.f);
    float vc = clampf(v[n], -1.f, 1.f);
    float th = clampf(theta[n], -2.f, 2.f) * TWOPI_F;
    float sr, cr;
    sincosf(th, &sr, &cr);

    float sg  = clampf(rsig[n], 1e-5f, 5.f);
    float gm  = clampf(gam[n],  1e-5f, 5.f);
    float i2s = -1.f / (2.f * sg * sg);
    float i2g = -1.f / (2.f * gm * gm);
    float fr  = TWOPI_F / expf(rfreq[n]);

    float A[3], nB[3];
    bool keep = false;
    #pragma unroll
    for (int c = 0; c < 3; ++c) {
        float a  = clampf(amp[3 * n + c], 0.f, 1.f);
        float ph = clampf(psi[3 * n + c], -1.f, 1.f) * TWOPI_F;
        float sp, cp;
        sincosf(ph, &sp, &cp);
        A[c]  =  a * cp;
        nB[c] = -a * sp;
        keep  = keep || (a > 0.f);
    }

    // deterministic compaction (ballot + per-warp prefix sum)
    unsigned m = __ballot_sync(0xffffffffu, keep);
    __shared__ int wcnt[8];
    int wid = n >> 5, lid = n & 31;
    if (lid == 0) wcnt[wid] = __popc(m);
    __syncthreads();
    int basew = 0;
    for (int w = 0; w < wid; ++w) basew += wcnt[w];
    if (keep) {
        int pos = basew + __popc(m & ((1u << lid) - 1u));
        g_p0[pos] = make_float4(uc, vc, cr, sr);
        g_p1[pos] = make_float4(i2s, i2g, fr, A[0]);
        g_p2[pos] = make_float4(A[1], A[2], nB[0], nB[1]);
        g_p3[pos] = nB[2];
    }
    __syncthreads();
    if (n == 0) {
        int tot = 0;
        #pragma unroll
        for (int w = 0; w < 8; ++w) tot += wcnt[w];
        g_cnt = tot;
    }
}

// ---- main kernel ---------------------------------------------------------------
__global__ void __launch_bounds__(TB)
gabor_kernel(const float* __restrict__ gx,
             const float* __restrict__ gy,
             float* __restrict__ out) {
    __shared__ float4 s_p0[NG];
    __shared__ float4 s_p1[NG];
    __shared__ float4 s_p2[NG];
    __shared__ float  s_p3[NG];

    int cnt = g_cnt;
    for (int i = threadIdx.x; i < cnt; i += TB) {
        s_p0[i] = g_p0[i];
        s_p1[i] = g_p1[i];
        s_p2[i] = g_p2[i];
        s_p3[i] = g_p3[i];
    }
    __syncthreads();

    const int idx = blockIdx.x * TB + threadIdx.x;
    const float px = gx[idx];
    const float py = gy[idx];
    float acc0 = 0.f, acc1 = 0.f, acc2 = 0.f;

    for (int n = 0; n < cnt; ++n) {
        float4 p0 = s_p0[n];
        float4 p1 = s_p1[n];

        float dx = px - p0.x;
        float dy = py - p0.y;
        float xr = fmaf(dx, p0.z, dy * p0.w);        //  dx*cr + dy*sr
        float yr = fmaf(dy, p0.z, -(dx * p0.w));     //  dy*cr - dx*sr
        float arg = fmaf(yr * yr, p1.y, (xr * xr) * p1.x);

        // warp-level skip: exp(-17)*|coef|*256 gabors <= ~1e-5 absolute — safe
        if (!__any_sync(0xffffffffu, arg > -17.0f)) continue;

        float4 p2  = s_p2[n];
        float  nB2 = s_p3[n];

        float g  = __expf(arg);      // arg <= 0 always; exp(-80 vs -huge) diff ~1e-35
        float fx = p1.z * xr;

        // range reduction to [-pi, pi]
        float r;
        if (fabsf(fx) < 1.0e7f) {
            // 2-term FMA Cody-Waite; k < 2^21 exact, residual k*RC3 ~ 2e-9 rad
            float k = rintf(fx * INV2PI_F);
            r = fmaf(k, -RC1, fx);
            r = fmaf(k, -RC2, r);
        } else {
            // rare extreme-frequency gabor: fp64 reduction
            double xd = (double)fx;
            double q  = rint(xd * INV2PI_D);
            r = (float)fma(q, -TWOPI_D, xd);
        }

        float s, c;
        __sincosf(r, &s, &c);   // |r| <= pi: MUFU accurate (~5e-7 abs)

        float gc = g * c;
        float gs = g * s;
        acc0 = fmaf(gc, p1.w, fmaf(gs, p2.z, acc0));
        acc1 = fmaf(gc, p2.x, fmaf(gs, p2.w, acc1));
        acc2 = fmaf(gc, p2.y, fmaf(gs, nB2,  acc2));
    }

    out[idx]          = clampf(acc0, -1.f, 1.f);
    out[HW + idx]     = clampf(acc1, -1.f, 1.f);
    out[2 * HW + idx] = clampf(acc2, -1.f, 1.f);
}

// ---- launch ----------------------------------------------------------------------
extern "C" void kernel_launch(void* const* d_in, const int* in_sizes, int n_in,
                              void* d_out, int out_size) {
    const float* gx    = (const float*)d_in[0];
    const float* gy    = (const float*)d_in[1];
    const float* u     = (const float*)d_in[2];
    const float* v     = (const float*)d_in[3];
    const float* theta = (const float*)d_in[4];
    const float* rsig  = (const float*)d_in[5];
    const float* rfreq = (const float*)d_in[6];
    const float* gam   = (const float*)d_in[7];
    const float* psi   = (const float*)d_in[8];
    const float* amp   = (const float*)d_in[9];
    float* out = (float*)d_out;

    prep_kernel<<<1, NG>>>(u, v, theta, rsig, rfreq, gam, psi, amp);
    gabor_kernel<<<NBLK, TB>>>(gx, gy, out);
}

// round 4
// speedup vs baseline: 1.1169x; 1.0839x over previous
#include <cuda_runtime.h>
#include <math.h>

#define NG   256
#define HGT  512
#define WID  512
#define HW   (HGT * WID)
#define TB   256
#define PPB  (TB * 2)          // pixels per block (2 per thread)
#define NBLK (HW / PPB)        // 512

// ---- constants -------------------------------------------------------------
constexpr double TWOPI_D  = 6.283185307179586476925286766559;
constexpr float  TWOPI_F  = (float)TWOPI_D;
constexpr float  RC1      = (float)TWOPI_D;
constexpr float  RC2      = (float)(TWOPI_D - (double)RC1);
constexpr float  INV2PI_F = (float)(1.0 / TWOPI_D);
constexpr double INV2PI_D = 1.0 / TWOPI_D;
constexpr float  L2E_F    = 1.4426950408889634f;   // rounds to 0x3FB8AA3B (== __expf's)

// ---- packed f32x2 helpers (each half bitwise identical to scalar op) --------
typedef unsigned long long F2;

__device__ __forceinline__ F2 f2pack(float lo, float hi) {
    F2 r; asm("mov.b64 %0, {%1, %2};" : "=l"(r) : "f"(lo), "f"(hi)); return r;
}
__device__ __forceinline__ void f2unpack(F2 v, float& lo, float& hi) {
    asm("mov.b64 {%0, %1}, %2;" : "=f"(lo), "=f"(hi) : "l"(v));
}
__device__ __forceinline__ F2 f2sub(F2 a, F2 b) {
    F2 r; asm("sub.rn.f32x2 %0, %1, %2;" : "=l"(r) : "l"(a), "l"(b)); return r;
}
__device__ __forceinline__ F2 f2mul(F2 a, F2 b) {
    F2 r; asm("mul.rn.f32x2 %0, %1, %2;" : "=l"(r) : "l"(a), "l"(b)); return r;
}
__device__ __forceinline__ F2 f2fma(F2 a, F2 b, F2 c) {
    F2 r; asm("fma.rn.f32x2 %0, %1, %2, %3;" : "=l"(r) : "l"(a), "l"(b), "l"(c)); return r;
}
__device__ __forceinline__ float ex2f(float x) {
    float r; asm("ex2.approx.f32 %0, %1;" : "=f"(r) : "f"(x)); return r;
}
__device__ __forceinline__ float sinaf(float x) {
    float r; asm("sin.approx.f32 %0, %1;" : "=f"(r) : "f"(x)); return r;
}
__device__ __forceinline__ float cosaf(float x) {
    float r; asm("cos.approx.f32 %0, %1;" : "=f"(r) : "f"(x)); return r;
}

// ---- device-global scratch ---------------------------------------------------
// 7 float4 per compacted gabor, every value DUPLICATED into an (x,x) pair so the
// main kernel reads packed broadcasts directly (no per-thread packing cost):
//   [7n+0]=(uc,uc,vc,vc)  [7n+1]=(cr,cr,sr,sr)    [7n+2]=(i2s,i2s,i2g,i2g)
//   [7n+3]=(fr,fr,A0,A0)  [7n+4]=(A1,A1,A2,A2)    [7n+5]=(nB0,nB0,nB1,nB1)
//   [7n+6]=(nB2,nB2,0,0)
// A_c = amp_c*cos(phase_c), nB_c = -amp_c*sin(phase_c), i2* = -1/(2 sig^2) etc.
__device__ float4 g_k[NG * 7];
__device__ int    g_cnt;

__device__ __forceinline__ float clampf(float x, float lo, float hi) {
    return fminf(fmaxf(x, lo), hi);
}

// ---- prep kernel: clamp params, build coefficients, compact dead gabors -----
__global__ void prep_kernel(const float* __restrict__ u,
                            const float* __restrict__ v,
                            const float* __restrict__ theta,
                            const float* __restrict__ rsig,
                            const float* __restrict__ rfreq,
                            const float* __restrict__ gam,
                            const float* __restrict__ psi,
                            const float* __restrict__ amp) {
    int n = threadIdx.x;   // 256 threads, 1 block

    float uc = clampf(u[n], -1.f, 1.f);
    float vc = clampf(v[n], -1.f, 1.f);
    float th = clampf(theta[n], -2.f, 2.f) * TWOPI_F;
    float sr, cr;
    sincosf(th, &sr, &cr);

    float sg  = clampf(rsig[n], 1e-5f, 5.f);
    float gm  = clampf(gam[n],  1e-5f, 5.f);
    float i2s = -1.f / (2.f * sg * sg);
    float i2g = -1.f / (2.f * gm * gm);
    float fr  = TWOPI_F / expf(rfreq[n]);

    float A[3], nB[3];
    bool keep = false;
    #pragma unroll
    for (int c = 0; c < 3; ++c) {
        float a  = clampf(amp[3 * n + c], 0.f, 1.f);
        float ph = clampf(psi[3 * n + c], -1.f, 1.f) * TWOPI_F;
        float sp, cp;
        sincosf(ph, &sp, &cp);
        A[c]  =  a * cp;
        nB[c] = -a * sp;
        keep  = keep || (a > 0.f);
    }

    // deterministic compaction (ballot + per-warp prefix sum)
    unsigned m = __ballot_sync(0xffffffffu, keep);
    __shared__ int wcnt[8];
    int wid = n >> 5, lid = n & 31;
    if (lid == 0) wcnt[wid] = __popc(m);
    __syncthreads();
    int basew = 0;
    for (int w = 0; w < wid; ++w) basew += wcnt[w];
    if (keep) {
        int p = basew + __popc(m & ((1u << lid) - 1u));
        g_k[7 * p + 0] = make_float4(uc,  uc,  vc,  vc);
        g_k[7 * p + 1] = make_float4(cr,  cr,  sr,  sr);
        g_k[7 * p + 2] = make_float4(i2s, i2s, i2g, i2g);
        g_k[7 * p + 3] = make_float4(fr,  fr,  A[0], A[0]);
        g_k[7 * p + 4] = make_float4(A[1], A[1], A[2], A[2]);
        g_k[7 * p + 5] = make_float4(nB[0], nB[0], nB[1], nB[1]);
        g_k[7 * p + 6] = make_float4(nB[2], nB[2], 0.f, 0.f);
    }
    __syncthreads();
    if (n == 0) {
        int tot = 0;
        #pragma unroll
        for (int w = 0; w < 8; ++w) tot += wcnt[w];
        g_cnt = tot;
    }
}

// ---- main kernel: 2 pixels per thread via packed f32x2 -------------------------
__global__ void __launch_bounds__(TB)
gabor_kernel(const float* __restrict__ gx,
             const float* __restrict__ gy,
             float* __restrict__ out) {
    __shared__ ulonglong2 s_k[NG * 7];   // each entry = one float4 = 2 packed pairs

    int cnt = g_cnt;
    {
        const ulonglong2* gk = reinterpret_cast<const ulonglong2*>(g_k);
        for (int i = threadIdx.x; i < 7 * cnt; i += TB) s_k[i] = gk[i];
    }
    __syncthreads();

    const int idx0 = blockIdx.x * PPB + threadIdx.x;
    const int idx1 = idx0 + TB;

    const F2 pxP = f2pack(gx[idx0], gx[idx1]);
    const F2 pyP = f2pack(gy[idx0], gy[idx1]);

    const F2 ZERO   = 0ULL;                          // (+0, +0)
    const F2 L2EP   = f2pack(L2E_F, L2E_F);
    const F2 I2PIP  = f2pack(INV2PI_F, INV2PI_F);
    const F2 RC1NP  = f2pack(-RC1, -RC1);
    const F2 RC2NP  = f2pack(-RC2, -RC2);

    F2 acc0 = 0ULL, acc1 = 0ULL, acc2 = 0ULL;

    for (int n = 0; n < cnt; ++n) {
        const ulonglong2* kn = &s_k[7 * n];
        ulonglong2 q0 = kn[0];   // (ucP, vcP)
        ulonglong2 q1 = kn[1];   // (crP, srP)
        ulonglong2 q2 = kn[2];   // (i2sP, i2gP)

        // bitwise-per-half identical to:  dx=px-uc; dy=py-vc;
        //   xr=fmaf(dx,cr,dy*sr); yr=fmaf(dy,cr,-(dx*sr));
        //   arg=fmaf(yr*yr,i2g,(xr*xr)*i2s);
        F2 dx = f2sub(pxP, q0.x);
        F2 dy = f2sub(pyP, q0.y);
        F2 xr = f2fma(dx, q1.x, f2mul(dy, q1.y));
        F2 yr = f2fma(dy, q1.x, f2sub(ZERO, f2mul(dx, q1.y)));
        F2 arg = f2fma(f2mul(yr, yr), q2.y, f2mul(f2mul(xr, xr), q2.x));

        float a0, a1;
        f2unpack(arg, a0, a1);
        // warp-level skip: dropped contributions < e^-17 each, total < ~1e-5
        if (!__any_sync(0xffffffffu, fmaxf(a0, a1) > -17.0f)) continue;

        ulonglong2 q3 = kn[3];   // (frP, A0P)
        ulonglong2 q4 = kn[4];   // (A1P, A2P)
        ulonglong2 q5 = kn[5];   // (nB0P, nB1P)
        ulonglong2 q6 = kn[6];   // (nB2P, --)

        // gaussian: exactly __expf(arg) per half
        float e0, e1;
        f2unpack(f2mul(arg, L2EP), e0, e1);
        float g0 = ex2f(e0), g1 = ex2f(e1);

        // carrier phase: fx = freq*xr, exactly as round-2
        F2 fxP = f2mul(q3.x, xr);
        float fx0, fx1;
        f2unpack(fxP, fx0, fx1);

        // 2-term FMA Cody-Waite reduction to [-pi, pi]
        float k0raw, k1raw;
        f2unpack(f2mul(fxP, I2PIP), k0raw, k1raw);
        F2 kP = f2pack(rintf(k0raw), rintf(k1raw));
        F2 rP = f2fma(kP, RC1NP, fxP);
        rP = f2fma(kP, RC2NP, rP);
        float r0, r1;
        f2unpack(rP, r0, r1);

        // rare extreme-frequency gabor: fp64 reduction per half
        if (fabsf(fx0) >= 1.0e7f) {
            double xd = (double)fx0, q = rint(xd * INV2PI_D);
            r0 = (float)fma(q, -TWOPI_D, xd);
        }
        if (fabsf(fx1) >= 1.0e7f) {
            double xd = (double)fx1, q = rint(xd * INV2PI_D);
            r1 = (float)fma(q, -TWOPI_D, xd);
        }

        float s0 = sinaf(r0), c0 = cosaf(r0);
        float s1 = sinaf(r1), c1 = cosaf(r1);

        F2 gcP = f2pack(g0 * c0, g1 * c1);
        F2 gsP = f2pack(g0 * s0, g1 * s1);

        acc0 = f2fma(gcP, q3.y, f2fma(gsP, q5.x, acc0));
        acc1 = f2fma(gcP, q4.x, f2fma(gsP, q5.y, acc1));
        acc2 = f2fma(gcP, q4.y, f2fma(gsP, q6.x, acc2));
    }

    float o00, o01, o10, o11, o20, o21;
    f2unpack(acc0, o00, o01);
    f2unpack(acc1, o10, o11);
    f2unpack(acc2, o20, o21);
    out[idx0]          = clampf(o00, -1.f, 1.f);
    out[idx1]          = clampf(o01, -1.f, 1.f);
    out[HW + idx0]     = clampf(o10, -1.f, 1.f);
    out[HW + idx1]     = clampf(o11, -1.f, 1.f);
    out[2 * HW + idx0] = clampf(o20, -1.f, 1.f);
    out[2 * HW + idx1] = clampf(o21, -1.f, 1.f);
}

// ---- launch ----------------------------------------------------------------------
extern "C" void kernel_launch(void* const* d_in, const int* in_sizes, int n_in,
                              void* d_out, int out_size) {
    const float* gx    = (const float*)d_in[0];
    const float* gy    = (const float*)d_in[1];
    const float* u     = (const float*)d_in[2];
    const float* v     = (const float*)d_in[3];
    const float* theta = (const float*)d_in[4];
    const float* rsig  = (const float*)d_in[5];
    const float* rfreq = (const float*)d_in[6];
    const float* gam   = (const float*)d_in[7];
    const float* psi   = (const float*)d_in[8];
    const float* amp   = (const float*)d_in[9];
    float* out = (float*)d_out;

    prep_kernel<<<1, NG>>>(u, v, theta, rsig, rfreq, gam, psi, amp);
    gabor_kernel<<<NBLK, TB>>>(gx, gy, out);
}